// round 2
// baseline (speedup 1.0000x reference)
#include <cuda_runtime.h>

// Problem constants
#define NSTEPS   8192
#define NPTS     8193            // positions per chain (leading zero row)
#define NCHAIN   2
#define CONFLEN  16388

// Tiling
#define IT       512             // i-tile size
#define NT       ((NPTS + IT - 1) / IT)      // 17
#define PADN     (NT * IT)                    // 8704
#define NP       (NT * (NT + 1) / 2)          // 153 tile pairs (tj >= ti)

#define PBLOCK   128             // pair-kernel threads
#define IPT      4               // i's per thread (IT = PBLOCK * IPT)
#define JC       128             // j chunk in smem (== PBLOCK)

// Scratch (no allocations allowed)
__device__ float4 g_pts[NCHAIN][PADN];       // (x_hat, y_hat, z_hat, a)
__device__ float  g_part[NCHAIN * NP];

// ---------------------------------------------------------------------------
// Setup: build positions (prefix sum of unit steps) and pre-scaled point data.
// One block (1024 threads) per chain; each thread handles 8 consecutive steps.
// ---------------------------------------------------------------------------
__global__ void setup_kernel(const float* __restrict__ conf) {
    const int chain = blockIdx.x;
    const float* cf = conf + chain * CONFLEN;
    const int t = threadIdx.x;                 // 0..1023
    const int lane = t & 31, warp = t >> 5;

    const float TWO_PI = 6.2831853071795864769f;

    // local steps + inclusive local prefix
    float px[8], py[8], pz[8];
    float sx = 0.f, sy = 0.f, sz = 0.f;
    const float2* cp = (const float2*)(cf + 4);  // (r1, r2) pairs
    #pragma unroll
    for (int m = 0; m < 8; m++) {
        int k = t * 8 + m;
        float2 rr = cp[k];
        float r1 = rr.x + 0.5f;
        float r2 = rr.y + 0.5f;
        float z  = 1.0f - 2.0f * r2;                    // cos(theta)
        float sth = sqrtf(fmaxf(1.0f - z * z, 0.0f));   // sin(theta)
        float s, c;
        sincosf(r1 * TWO_PI, &s, &c);
        sx += sth * c;
        sy += sth * s;
        sz += z;
        px[m] = sx; py[m] = sy; pz[m] = sz;
    }

    // warp inclusive scan of thread totals
    float tx = sx, ty = sy, tz = sz;
    #pragma unroll
    for (int d = 1; d < 32; d <<= 1) {
        float ox = __shfl_up_sync(0xffffffffu, tx, d);
        float oy = __shfl_up_sync(0xffffffffu, ty, d);
        float oz = __shfl_up_sync(0xffffffffu, tz, d);
        if (lane >= d) { tx += ox; ty += oy; tz += oz; }
    }

    __shared__ float3 wtot[32];
    __shared__ float3 woff[32];
    if (lane == 31) wtot[warp] = make_float3(tx, ty, tz);
    __syncthreads();
    if (t == 0) {
        float ax = 0.f, ay = 0.f, az = 0.f;
        #pragma unroll
        for (int w = 0; w < 32; w++) {
            float3 v = wtot[w];
            woff[w] = make_float3(ax, ay, az);
            ax += v.x; ay += v.y; az += v.z;
        }
    }
    __syncthreads();

    // exclusive base for this thread
    float bx = woff[warp].x + (tx - sx);
    float by = woff[warp].y + (ty - sy);
    float bz = woff[warp].z + (tz - sz);

    // arg = a_i + a_j + dot(p_hat_i, p_hat_j), with p_hat = SS*p, a = -0.5*|p_hat|^2
    const float S2 = 8.0f * 1.4426950408889634f;   // 8*log2(e)
    const float SS = sqrtf(S2);

    #pragma unroll
    for (int m = 0; m < 8; m++) {
        float x = bx + px[m];
        float y = by + py[m];
        float z = bz + pz[m];
        float xh = SS * x, yh = SS * y, zh = SS * z;
        float a = -0.5f * (xh * xh + yh * yh + zh * zh);
        g_pts[chain][t * 8 + m + 1] = make_float4(xh, yh, zh, a);
    }
    if (t == 0) g_pts[chain][0] = make_float4(0.f, 0.f, 0.f, 0.f);
    // padding points: contribute exactly 0 (ex2 of -1e30 underflows to 0)
    if (t < PADN - NPTS) g_pts[chain][NPTS + t] = make_float4(0.f, 0.f, 0.f, -1e30f);
}

// ---------------------------------------------------------------------------
// Pair kernel: strict upper triangle (j > i) over tile pairs (ti, tj), tj>=ti.
// Each thread holds IPT i-points in registers, block streams j via smem.
// ---------------------------------------------------------------------------
__global__ void __launch_bounds__(PBLOCK) pair_kernel() {
    const int p = blockIdx.x;
    const int chain = blockIdx.y;

    // map linear pair index -> (ti, tj)
    int ti = 0, rem = p;
    while (rem >= NT - ti) { rem -= NT - ti; ti++; }
    const int tj = ti + rem;
    const bool diag = (ti == tj);

    const float4* __restrict__ pts = g_pts[chain];
    const int tid = threadIdx.x;
    const int ibase = ti * IT;

    float4 ipt[IPT];
    #pragma unroll
    for (int k = 0; k < IPT; k++)
        ipt[k] = pts[ibase + tid + k * PBLOCK];

    __shared__ float4 tj_sm[JC];
    float acc[IPT];
    #pragma unroll
    for (int k = 0; k < IPT; k++) acc[k] = 0.f;

    const int jbase0 = tj * IT;
    for (int jc = 0; jc < IT; jc += JC) {
        tj_sm[tid] = pts[jbase0 + jc + tid];
        __syncthreads();

        if (!diag) {
            #pragma unroll 4
            for (int jj = 0; jj < JC; jj++) {
                float4 q = tj_sm[jj];
                #pragma unroll
                for (int k = 0; k < IPT; k++) {
                    float m = fmaf(ipt[k].x, q.x, q.w);
                    m = fmaf(ipt[k].y, q.y, m);
                    m = fmaf(ipt[k].z, q.z, m);
                    float arg = fminf(m + ipt[k].w, 0.0f);  // matches maximum(d2,0)
                    float e;
                    asm("ex2.approx.f32 %0, %1;" : "=f"(e) : "f"(arg));
                    acc[k] += e;
                }
            }
        } else {
            #pragma unroll 4
            for (int jj = 0; jj < JC; jj++) {
                float4 q = tj_sm[jj];
                int j = jbase0 + jc + jj;
                #pragma unroll
                for (int k = 0; k < IPT; k++) {
                    int i = ibase + tid + k * PBLOCK;
                    float m = fmaf(ipt[k].x, q.x, q.w);
                    m = fmaf(ipt[k].y, q.y, m);
                    m = fmaf(ipt[k].z, q.z, m);
                    float arg = fminf(m + ipt[k].w, 0.0f);
                    float e;
                    asm("ex2.approx.f32 %0, %1;" : "=f"(e) : "f"(arg));
                    acc[k] += (j > i) ? e : 0.0f;
                }
            }
        }
        __syncthreads();
    }

    float s = 0.f;
    #pragma unroll
    for (int k = 0; k < IPT; k++) s += acc[k];

    // block reduction
    #pragma unroll
    for (int d = 16; d > 0; d >>= 1)
        s += __shfl_down_sync(0xffffffffu, s, d);
    __shared__ float red[PBLOCK / 32];
    if ((tid & 31) == 0) red[tid >> 5] = s;
    __syncthreads();
    if (tid == 0) {
        float tot = 0.f;
        #pragma unroll
        for (int w = 0; w < PBLOCK / 32; w++) tot += red[w];
        g_part[chain * NP + p] = tot;
    }
}

// ---------------------------------------------------------------------------
// Final deterministic reduction: out = SIGMA * (2*offdiag + n_diag)
// ---------------------------------------------------------------------------
__global__ void reduce_kernel(float* __restrict__ out) {
    const int tid = threadIdx.x;
    double s = 0.0;
    for (int i = tid; i < NCHAIN * NP; i += 256) s += (double)g_part[i];

    #pragma unroll
    for (int d = 16; d > 0; d >>= 1)
        s += __shfl_down_sync(0xffffffffu, s, d);
    __shared__ double red[8];
    if ((tid & 31) == 0) red[tid >> 5] = s;
    __syncthreads();
    if (tid == 0) {
        double tot = 0.0;
        #pragma unroll
        for (int w = 0; w < 8; w++) tot += red[w];
        double result = 10.0 * (2.0 * tot + (double)(NCHAIN * NPTS));
        out[0] = (float)result;
    }
}

extern "C" void kernel_launch(void* const* d_in, const int* in_sizes, int n_in,
                              void* d_out, int out_size) {
    const float* conf = (const float*)d_in[0];
    float* out = (float*)d_out;

    setup_kernel<<<NCHAIN, 1024>>>(conf);
    pair_kernel<<<dim3(NP, NCHAIN), PBLOCK>>>();
    reduce_kernel<<<1, 256>>>(out);
}

// round 3
// speedup vs baseline: 1.0999x; 1.0999x over previous
#include <cuda_runtime.h>

// Problem constants
#define NSTEPS   8192
#define NPTS     8193            // positions per chain (incl. leading zero row)
#define NCHAIN   2
#define CONFLEN  16388

// Chunking
#define CHUNK    128
#define NCHUNK   68                              // PADN / CHUNK
#define PADN     (NCHUNK * CHUNK)                // 8704
#define NPAIR    (NCHUNK * (NCHUNK + 1) / 2)     // 2346 chunk pairs (cj >= ci)

#define PBLOCK   128

// Scaled-space cutoff: dropped pair value <= 2^(-0.5*64) = 2.3e-10
#define DCUT_HAT 8.0f

// Scratch (no allocations allowed)
__device__ float4 g_pts[NCHAIN][PADN];           // (x_hat, y_hat, z_hat, a)
__device__ float4 g_cb[NCHAIN * NCHUNK];         // chunk bounds: (cx,cy,cz,r)
__device__ float  g_part[NCHAIN * NPAIR];

// ---------------------------------------------------------------------------
// Setup: build positions (prefix sum of unit steps), pre-scale, write pads.
// One block (1024 threads) per chain; each thread handles 8 consecutive steps.
// ---------------------------------------------------------------------------
__global__ void setup_kernel(const float* __restrict__ conf) {
    const int chain = blockIdx.x;
    const float* cf = conf + chain * CONFLEN;
    const int t = threadIdx.x;                 // 0..1023
    const int lane = t & 31, warp = t >> 5;

    const float TWO_PI = 6.2831853071795864769f;

    // local steps + inclusive local prefix
    float px[8], py[8], pz[8];
    float sx = 0.f, sy = 0.f, sz = 0.f;
    const float2* cp = (const float2*)(cf + 4);  // (r1, r2) pairs
    #pragma unroll
    for (int m = 0; m < 8; m++) {
        int k = t * 8 + m;
        float2 rr = cp[k];
        float r1 = rr.x + 0.5f;
        float r2 = rr.y + 0.5f;
        float z  = 1.0f - 2.0f * r2;                    // cos(theta)
        float sth = sqrtf(fmaxf(1.0f - z * z, 0.0f));   // sin(theta)
        float s, c;
        __sincosf(r1 * TWO_PI, &s, &c);
        sx += sth * c;
        sy += sth * s;
        sz += z;
        px[m] = sx; py[m] = sy; pz[m] = sz;
    }

    // warp inclusive scan of thread totals
    float tx = sx, ty = sy, tz = sz;
    #pragma unroll
    for (int d = 1; d < 32; d <<= 1) {
        float ox = __shfl_up_sync(0xffffffffu, tx, d);
        float oy = __shfl_up_sync(0xffffffffu, ty, d);
        float oz = __shfl_up_sync(0xffffffffu, tz, d);
        if (lane >= d) { tx += ox; ty += oy; tz += oz; }
    }

    __shared__ float3 wtot[32];
    __shared__ float3 woff[32];
    __shared__ float4 lastpt;
    if (lane == 31) wtot[warp] = make_float3(tx, ty, tz);
    __syncthreads();
    if (t == 0) {
        float ax = 0.f, ay = 0.f, az = 0.f;
        #pragma unroll
        for (int w = 0; w < 32; w++) {
            float3 v = wtot[w];
            woff[w] = make_float3(ax, ay, az);
            ax += v.x; ay += v.y; az += v.z;
        }
    }
    __syncthreads();

    // exclusive base for this thread
    float bx = woff[warp].x + (tx - sx);
    float by = woff[warp].y + (ty - sy);
    float bz = woff[warp].z + (tz - sz);

    // arg = a_i + a_j + dot(p_hat_i, p_hat_j), p_hat = SS*p, a = -0.5*|p_hat|^2
    const float S2 = 8.0f * 1.4426950408889634f;   // 8*log2(e)
    const float SS = sqrtf(S2);

    float4 mylast;
    #pragma unroll
    for (int m = 0; m < 8; m++) {
        float x = bx + px[m];
        float y = by + py[m];
        float z = bz + pz[m];
        float xh = SS * x, yh = SS * y, zh = SS * z;
        float a = -0.5f * (xh * xh + yh * yh + zh * zh);
        mylast = make_float4(xh, yh, zh, a);
        g_pts[chain][t * 8 + m + 1] = mylast;
    }
    if (t == 0) g_pts[chain][0] = make_float4(0.f, 0.f, 0.f, 0.f);
    if (t == 1023) lastpt = mylast;    // point index 8192 = last real point
    __syncthreads();

    // padding points: same position as last real point (keeps last chunk's
    // bounding sphere tight), a = -1e30 -> exp2 underflows to exactly 0.
    if (t < PADN - NPTS)
        g_pts[chain][NPTS + t] =
            make_float4(lastpt.x, lastpt.y, lastpt.z, -1e30f);
}

// ---------------------------------------------------------------------------
// Bounds: per 128-point chunk, compute bounding sphere in scaled space.
// ---------------------------------------------------------------------------
__global__ void bounds_kernel() {
    const int chunk = blockIdx.x, chain = blockIdx.y;
    const int tid = threadIdx.x, lane = tid & 31, warp = tid >> 5;

    float4 p = g_pts[chain][chunk * CHUNK + tid];
    float mnx = p.x, mxx = p.x, mny = p.y, mxy = p.y, mnz = p.z, mxz = p.z;

    #pragma unroll
    for (int d = 16; d > 0; d >>= 1) {
        mnx = fminf(mnx, __shfl_xor_sync(0xffffffffu, mnx, d));
        mxx = fmaxf(mxx, __shfl_xor_sync(0xffffffffu, mxx, d));
        mny = fminf(mny, __shfl_xor_sync(0xffffffffu, mny, d));
        mxy = fmaxf(mxy, __shfl_xor_sync(0xffffffffu, mxy, d));
        mnz = fminf(mnz, __shfl_xor_sync(0xffffffffu, mnz, d));
        mxz = fmaxf(mxz, __shfl_xor_sync(0xffffffffu, mxz, d));
    }
    __shared__ float smn[3][4], smx[3][4];
    __shared__ float3 ctr;
    if (lane == 0) {
        smn[0][warp] = mnx; smn[1][warp] = mny; smn[2][warp] = mnz;
        smx[0][warp] = mxx; smx[1][warp] = mxy; smx[2][warp] = mxz;
    }
    __syncthreads();
    if (tid == 0) {
        float a0 = smn[0][0], a1 = smn[1][0], a2 = smn[2][0];
        float b0 = smx[0][0], b1 = smx[1][0], b2 = smx[2][0];
        #pragma unroll
        for (int w = 1; w < 4; w++) {
            a0 = fminf(a0, smn[0][w]); a1 = fminf(a1, smn[1][w]); a2 = fminf(a2, smn[2][w]);
            b0 = fmaxf(b0, smx[0][w]); b1 = fmaxf(b1, smx[1][w]); b2 = fmaxf(b2, smx[2][w]);
        }
        ctr = make_float3(0.5f * (a0 + b0), 0.5f * (a1 + b1), 0.5f * (a2 + b2));
    }
    __syncthreads();

    float dx = p.x - ctr.x, dy = p.y - ctr.y, dz = p.z - ctr.z;
    float d2 = dx * dx + dy * dy + dz * dz;
    #pragma unroll
    for (int d = 16; d > 0; d >>= 1)
        d2 = fmaxf(d2, __shfl_xor_sync(0xffffffffu, d2, d));
    __shared__ float wd2[4];
    if (lane == 0) wd2[warp] = d2;
    __syncthreads();
    if (tid == 0) {
        float m = fmaxf(fmaxf(wd2[0], wd2[1]), fmaxf(wd2[2], wd2[3]));
        g_cb[chain * NCHUNK + chunk] =
            make_float4(ctr.x, ctr.y, ctr.z, sqrtf(m) * 1.0001f + 1e-3f);
    }
}

// ---------------------------------------------------------------------------
// Pair kernel: one block per chunk pair (cj >= ci), bounding-sphere cull,
// strict upper triangle (global j > global i) via local mask on diagonal.
// ---------------------------------------------------------------------------
__global__ void __launch_bounds__(PBLOCK) pair_kernel() {
    const int p = blockIdx.x;
    const int chain = blockIdx.y;
    const int tid = threadIdx.x;

    // map linear pair index -> (ci, cj)
    int ci = 0, rem = p;
    while (rem >= NCHUNK - ci) { rem -= NCHUNK - ci; ci++; }
    const int cj = ci + rem;

    // bounding-sphere cull
    float4 bi = g_cb[chain * NCHUNK + ci];
    float4 bj = g_cb[chain * NCHUNK + cj];
    float dcx = bi.x - bj.x, dcy = bi.y - bj.y, dcz = bi.z - bj.z;
    float rr = bi.w + bj.w + DCUT_HAT;
    if (dcx * dcx + dcy * dcy + dcz * dcz > rr * rr) {
        if (tid == 0) g_part[chain * NPAIR + p] = 0.f;
        return;
    }

    const float4* __restrict__ pts = g_pts[chain];
    float4 ipt = pts[ci * CHUNK + tid];

    __shared__ float4 tj_sm[CHUNK];
    tj_sm[tid] = pts[cj * CHUNK + tid];
    __syncthreads();

    float acc = 0.f;
    if (ci != cj) {
        #pragma unroll 8
        for (int jj = 0; jj < CHUNK; jj++) {
            float4 q = tj_sm[jj];
            float m = fmaf(ipt.x, q.x, q.w);
            m = fmaf(ipt.y, q.y, m);
            m = fmaf(ipt.z, q.z, m);
            float arg = fminf(m + ipt.w, 0.0f);
            float e;
            asm("ex2.approx.f32 %0, %1;" : "=f"(e) : "f"(arg));
            acc += e;
        }
    } else {
        #pragma unroll 8
        for (int jj = 0; jj < CHUNK; jj++) {
            float4 q = tj_sm[jj];
            float m = fmaf(ipt.x, q.x, q.w);
            m = fmaf(ipt.y, q.y, m);
            m = fmaf(ipt.z, q.z, m);
            float arg = fminf(m + ipt.w, 0.0f);
            float e;
            asm("ex2.approx.f32 %0, %1;" : "=f"(e) : "f"(arg));
            acc += (jj > tid) ? e : 0.0f;
        }
    }

    // block reduction
    #pragma unroll
    for (int d = 16; d > 0; d >>= 1)
        acc += __shfl_down_sync(0xffffffffu, acc, d);
    __shared__ float red[PBLOCK / 32];
    if ((tid & 31) == 0) red[tid >> 5] = acc;
    __syncthreads();
    if (tid == 0) {
        float tot = 0.f;
        #pragma unroll
        for (int w = 0; w < PBLOCK / 32; w++) tot += red[w];
        g_part[chain * NPAIR + p] = tot;
    }
}

// ---------------------------------------------------------------------------
// Final deterministic reduction: out = SIGMA * (2*offdiag + n_diag)
// ---------------------------------------------------------------------------
__global__ void reduce_kernel(float* __restrict__ out) {
    const int tid = threadIdx.x;
    double s = 0.0;
    for (int i = tid; i < NCHAIN * NPAIR; i += 256) s += (double)g_part[i];

    #pragma unroll
    for (int d = 16; d > 0; d >>= 1)
        s += __shfl_down_sync(0xffffffffu, s, d);
    __shared__ double red[8];
    if ((tid & 31) == 0) red[tid >> 5] = s;
    __syncthreads();
    if (tid == 0) {
        double tot = 0.0;
        #pragma unroll
        for (int w = 0; w < 8; w++) tot += red[w];
        double result = 10.0 * (2.0 * tot + (double)(NCHAIN * NPTS));
        out[0] = (float)result;
    }
}

extern "C" void kernel_launch(void* const* d_in, const int* in_sizes, int n_in,
                              void* d_out, int out_size) {
    const float* conf = (const float*)d_in[0];
    float* out = (float*)d_out;

    setup_kernel<<<NCHAIN, 1024>>>(conf);
    bounds_kernel<<<dim3(NCHUNK, NCHAIN), CHUNK>>>();
    pair_kernel<<<dim3(NPAIR, NCHAIN), PBLOCK>>>();
    reduce_kernel<<<1, 256>>>(out);
}

// round 4
// speedup vs baseline: 1.9034x; 1.7304x over previous
#include <cuda_runtime.h>

// Problem constants
#define NSTEPS   8192
#define NPTS     8193            // positions per chain (incl. leading zero row)
#define NCHAIN   2
#define CONFLEN  16388

// Chunking
#define CHUNK    128
#define NCHUNK   68                              // PADN / CHUNK
#define PADN     (NCHUNK * CHUNK)                // 8704
#define NPAIR    (NCHUNK * (NCHUNK + 1) / 2)     // 2346 chunk pairs (cj >= ci)
#define NBLOCKS  (NPAIR * NCHAIN)                // 4692

#define PBLOCK   128

// Scaled-space cutoff: dropped pair value <= 2^(-0.5*64) = 2.3e-10
#define DCUT_HAT 8.0f

// Fixed-point scale for deterministic integer accumulation
#define FXSCALE  16777216.0f     // 2^24

// Scratch (no allocations allowed; zero-initialized)
__device__ float4 g_pts[NCHAIN][PADN];           // (x_hat, y_hat, z_hat, a)
__device__ float4 g_cb[NCHAIN * NCHUNK];         // chunk bounds: (cx,cy,cz,r)
__device__ unsigned long long g_acc;             // fixed-point sum
__device__ unsigned int g_count;                 // finished-block counter

// ---------------------------------------------------------------------------
// Setup: positions (prefix sum of unit steps), pre-scale, pads, chunk bounds.
// One block (1024 threads) per chain; each thread handles 8 consecutive steps.
// ---------------------------------------------------------------------------
__global__ void setup_kernel(const float* __restrict__ conf) {
    const int chain = blockIdx.x;
    const float* cf = conf + chain * CONFLEN;
    const int t = threadIdx.x;                 // 0..1023
    const int lane = t & 31, warp = t >> 5;

    const float TWO_PI = 6.2831853071795864769f;

    // local steps + inclusive local prefix
    float px[8], py[8], pz[8];
    float sx = 0.f, sy = 0.f, sz = 0.f;
    const float2* cp = (const float2*)(cf + 4);  // (r1, r2) pairs
    #pragma unroll
    for (int m = 0; m < 8; m++) {
        int k = t * 8 + m;
        float2 rr = cp[k];
        float r1 = rr.x + 0.5f;
        float r2 = rr.y + 0.5f;
        float z  = 1.0f - 2.0f * r2;                    // cos(theta)
        float sth = sqrtf(fmaxf(1.0f - z * z, 0.0f));   // sin(theta)
        float s, c;
        __sincosf(r1 * TWO_PI, &s, &c);
        sx += sth * c;
        sy += sth * s;
        sz += z;
        px[m] = sx; py[m] = sy; pz[m] = sz;
    }

    // warp inclusive scan of thread totals
    float tx = sx, ty = sy, tz = sz;
    #pragma unroll
    for (int d = 1; d < 32; d <<= 1) {
        float ox = __shfl_up_sync(0xffffffffu, tx, d);
        float oy = __shfl_up_sync(0xffffffffu, ty, d);
        float oz = __shfl_up_sync(0xffffffffu, tz, d);
        if (lane >= d) { tx += ox; ty += oy; tz += oz; }
    }

    __shared__ float3 wtot[32];
    __shared__ float3 woff[32];
    __shared__ float4 lastpt;
    if (lane == 31) wtot[warp] = make_float3(tx, ty, tz);
    __syncthreads();
    if (t == 0) {
        float ax = 0.f, ay = 0.f, az = 0.f;
        #pragma unroll
        for (int w = 0; w < 32; w++) {
            float3 v = wtot[w];
            woff[w] = make_float3(ax, ay, az);
            ax += v.x; ay += v.y; az += v.z;
        }
    }
    __syncthreads();

    // exclusive base for this thread
    float bx = woff[warp].x + (tx - sx);
    float by = woff[warp].y + (ty - sy);
    float bz = woff[warp].z + (tz - sz);

    // arg = a_i + a_j + dot(p_hat_i, p_hat_j), p_hat = SS*p, a = -0.5*|p_hat|^2
    const float S2 = 8.0f * 1.4426950408889634f;   // 8*log2(e)
    const float SS = sqrtf(S2);                    // ~3.397 (scaled step length)

    float4 mylast;
    float mnx = 1e30f, mxx = -1e30f, mny = 1e30f, mxy = -1e30f;
    float mnz = 1e30f, mxz = -1e30f;
    #pragma unroll
    for (int m = 0; m < 8; m++) {
        float x = bx + px[m];
        float y = by + py[m];
        float z = bz + pz[m];
        float xh = SS * x, yh = SS * y, zh = SS * z;
        float a = -0.5f * (xh * xh + yh * yh + zh * zh);
        mylast = make_float4(xh, yh, zh, a);
        g_pts[chain][t * 8 + m + 1] = mylast;
        mnx = fminf(mnx, xh); mxx = fmaxf(mxx, xh);
        mny = fminf(mny, yh); mxy = fmaxf(mxy, yh);
        mnz = fminf(mnz, zh); mxz = fmaxf(mxz, zh);
    }
    if (t == 0) g_pts[chain][0] = make_float4(0.f, 0.f, 0.f, 0.f);
    if (t == 1023) lastpt = mylast;    // point index 8192 = last real point

    // per-chunk bounds: 16-thread segments hold points [128c+1, 128c+129);
    // radius inflated by SS (one step) to cover boundary point 128c.
    #pragma unroll
    for (int d = 8; d > 0; d >>= 1) {
        mnx = fminf(mnx, __shfl_xor_sync(0xffffffffu, mnx, d, 16));
        mxx = fmaxf(mxx, __shfl_xor_sync(0xffffffffu, mxx, d, 16));
        mny = fminf(mny, __shfl_xor_sync(0xffffffffu, mny, d, 16));
        mxy = fmaxf(mxy, __shfl_xor_sync(0xffffffffu, mxy, d, 16));
        mnz = fminf(mnz, __shfl_xor_sync(0xffffffffu, mnz, d, 16));
        mxz = fmaxf(mxz, __shfl_xor_sync(0xffffffffu, mxz, d, 16));
    }
    if ((t & 15) == 0) {
        float hx = 0.5f * (mxx - mnx), hy = 0.5f * (mxy - mny), hz = 0.5f * (mxz - mnz);
        float r = sqrtf(hx * hx + hy * hy + hz * hz) + SS + 1e-2f;
        g_cb[chain * NCHUNK + (t >> 4)] = make_float4(
            0.5f * (mnx + mxx), 0.5f * (mny + mxy), 0.5f * (mnz + mxz), r);
    }
    __syncthreads();

    // padding points at last real point (a=-1e30 -> contribute exactly 0)
    if (t < PADN - NPTS)
        g_pts[chain][NPTS + t] =
            make_float4(lastpt.x, lastpt.y, lastpt.z, -1e30f);

    // chunk 64 contains real point 8192 (= lastpt) + pads at lastpt
    if (t == 0)
        g_cb[chain * NCHUNK + 64] = make_float4(lastpt.x, lastpt.y, lastpt.z, 0.1f);
    // chunks 65..67 are pure pads: far-away center -> every pair culls
    if (t >= 1 && t <= 3)
        g_cb[chain * NCHUNK + 64 + t] = make_float4(2e15f, 2e15f, 2e15f, 0.f);
}

// ---------------------------------------------------------------------------
// Pair kernel: one block per chunk pair (cj >= ci), bounding-sphere cull,
// strict upper triangle on the diagonal; fixed-point atomic accumulation;
// last block finalizes output and resets state for the next graph replay.
// ---------------------------------------------------------------------------
__global__ void __launch_bounds__(PBLOCK) pair_kernel(float* __restrict__ out) {
    const int p = blockIdx.x;
    const int chain = blockIdx.y;
    const int tid = threadIdx.x;

    // map linear pair index -> (ci, cj)
    int ci = 0, rem = p;
    while (rem >= NCHUNK - ci) { rem -= NCHUNK - ci; ci++; }
    const int cj = ci + rem;

    // bounding-sphere cull
    float4 bi = g_cb[chain * NCHUNK + ci];
    float4 bj = g_cb[chain * NCHUNK + cj];
    float dcx = bi.x - bj.x, dcy = bi.y - bj.y, dcz = bi.z - bj.z;
    float rr = bi.w + bj.w + DCUT_HAT;
    const bool live = (dcx * dcx + dcy * dcy + dcz * dcz <= rr * rr);

    float tot = 0.f;
    if (live) {
        const float4* __restrict__ pts = g_pts[chain];
        float4 ipt = pts[ci * CHUNK + tid];

        __shared__ float4 tj_sm[CHUNK];
        tj_sm[tid] = pts[cj * CHUNK + tid];
        __syncthreads();

        float acc = 0.f;
        if (ci != cj) {
            #pragma unroll 8
            for (int jj = 0; jj < CHUNK; jj++) {
                float4 q = tj_sm[jj];
                float m = fmaf(ipt.x, q.x, q.w);
                m = fmaf(ipt.y, q.y, m);
                m = fmaf(ipt.z, q.z, m);
                float arg = fminf(m + ipt.w, 0.0f);
                float e;
                asm("ex2.approx.f32 %0, %1;" : "=f"(e) : "f"(arg));
                acc += e;
            }
        } else {
            #pragma unroll 8
            for (int jj = 0; jj < CHUNK; jj++) {
                float4 q = tj_sm[jj];
                float m = fmaf(ipt.x, q.x, q.w);
                m = fmaf(ipt.y, q.y, m);
                m = fmaf(ipt.z, q.z, m);
                float arg = fminf(m + ipt.w, 0.0f);
                float e;
                asm("ex2.approx.f32 %0, %1;" : "=f"(e) : "f"(arg));
                acc += (jj > tid) ? e : 0.0f;
            }
        }

        // block reduction
        #pragma unroll
        for (int d = 16; d > 0; d >>= 1)
            acc += __shfl_down_sync(0xffffffffu, acc, d);
        __shared__ float red[PBLOCK / 32];
        if ((tid & 31) == 0) red[tid >> 5] = acc;
        __syncthreads();
        if (tid == 0) {
            tot = red[0] + red[1] + red[2] + red[3];
        }
    }

    if (tid == 0) {
        if (live && tot > 0.f) {
            unsigned long long q = (unsigned long long)__float2ll_rn(tot * FXSCALE);
            atomicAdd(&g_acc, q);
        }
        __threadfence();
        unsigned int done = atomicAdd(&g_count, 1u);
        if (done == NBLOCKS - 1) {
            unsigned long long raw = atomicAdd(&g_acc, 0ULL);
            double sum = (double)(long long)raw * (1.0 / (double)FXSCALE);
            out[0] = (float)(10.0 * (2.0 * sum + (double)(NCHAIN * NPTS)));
            // reset for next graph replay
            atomicExch(&g_acc, 0ULL);
            atomicExch(&g_count, 0u);
        }
    }
}

extern "C" void kernel_launch(void* const* d_in, const int* in_sizes, int n_in,
                              void* d_out, int out_size) {
    const float* conf = (const float*)d_in[0];
    float* out = (float*)d_out;

    setup_kernel<<<NCHAIN, 1024>>>(conf);
    pair_kernel<<<dim3(NPAIR, NCHAIN), PBLOCK>>>(out);
}